// round 9
// baseline (speedup 1.0000x reference)
#include <cuda_runtime.h>
#include <cuda_bf16.h>
#include <math.h>
#include <stdint.h>

#define SEQ 2048
#define HIDDEN 4096
#define NQH 32
#define NKVH 8
#define HD 128
#define QDIM (NQH*HD)      /* 4096 */
#define KVDIM (NKVH*HD)    /* 1024 */
#define WINDOW 1024
#define SCALING 0.08838834764831845f

/* ---------------- scratch (__device__ globals; allocation-free rule) ---------------- */
__device__ float g_q[SEQ*QDIM];
__device__ float g_k[SEQ*KVDIM];
__device__ float g_v[SEQ*KVDIM];
/* bf16 hi/lo operands for the projection GEMMs */
__device__ __nv_bfloat16 g_hsh[SEQ*HIDDEN],  g_hsl[SEQ*HIDDEN];
__device__ __nv_bfloat16 g_wqh[QDIM*HIDDEN], g_wql[QDIM*HIDDEN];   /* [N][K] */
__device__ __nv_bfloat16 g_wkh[KVDIM*HIDDEN],g_wkl[KVDIM*HIDDEN];
__device__ __nv_bfloat16 g_wvh[KVDIM*HIDDEN],g_wvl[KVDIM*HIDDEN];
__device__ __nv_bfloat16 g_woh[HIDDEN*QDIM], g_wol[HIDDEN*QDIM];
__device__ __nv_bfloat16 g_ath[SEQ*QDIM],    g_atl[SEQ*QDIM];      /* attention out hi/lo */

/* ---------------- bf16 hi/lo split helpers ---------------- */
__device__ __forceinline__ void split2(float x, float y, uint32_t& hi, uint32_t& lo) {
    __nv_bfloat162 h = __float22bfloat162_rn(make_float2(x, y));
    float rx = x - __bfloat162float(h.x);
    float ry = y - __bfloat162float(h.y);
    __nv_bfloat162 l = __float22bfloat162_rn(make_float2(rx, ry));
    hi = *(uint32_t*)&h;
    lo = *(uint32_t*)&l;
}

__global__ void split_a_kernel(const float* __restrict__ in,
                               __nv_bfloat16* __restrict__ oh, __nv_bfloat16* __restrict__ ol, int n4)
{
    int i = blockIdx.x * blockDim.x + threadIdx.x;
    if (i >= n4) return;
    float4 v = ((const float4*)in)[i];
    uint32_t h01, l01, h23, l23;
    split2(v.x, v.y, h01, l01);
    split2(v.z, v.w, h23, l23);
    ((uint2*)oh)[i] = make_uint2(h01, h23);
    ((uint2*)ol)[i] = make_uint2(l01, l23);
}

/* transpose + split: W fp32 [K][N] -> bf16 hi/lo [N][K] */
__global__ void split_bt_kernel(const float* __restrict__ W,
                                __nv_bfloat16* __restrict__ oh, __nv_bfloat16* __restrict__ ol,
                                int K, int N)
{
    __shared__ float s[32][33];
    int k0 = blockIdx.y * 32, n0 = blockIdx.x * 32;
    int tx = threadIdx.x, ty = threadIdx.y;
    #pragma unroll
    for (int i = ty; i < 32; i += 8)
        s[i][tx] = W[(size_t)(k0 + i) * N + n0 + tx];
    __syncthreads();
    #pragma unroll
    for (int i = ty; i < 32; i += 8) {
        float v = s[tx][i];
        __nv_bfloat16 hb = __float2bfloat16_rn(v);
        float r = v - __bfloat162float(hb);
        oh[(size_t)(n0 + i) * K + k0 + tx] = hb;
        ol[(size_t)(n0 + i) * K + k0 + tx] = __float2bfloat16_rn(r);
    }
}

/* ---------------- bf16x3 GEMM: 128x256 CTA, 8 warps (64x64), 2-stage cp.async --------- */
/* C[M,N] = A[M,K] @ B^T, A row-major [M][K] bf16 hi/lo, B [N][K] bf16 hi/lo.            */

#define GBM 128
#define GBN 256
#define GBK 64              /* bf16 elements per stage */
#define AW 32               /* words per row (GBK/2) */
#define STRW 36             /* smem word stride: bank = 4*row + t4, conflict-free */
#define A_ST (GBM*STRW)     /* 4608 words */
#define B_ST (GBN*STRW)     /* 9216 words */
#define STAGE_W (2*A_ST + 2*B_ST)   /* Ah,Al,Bh,Bl = 27648 words */
#define GEMM_SMEM (2*STAGE_W*4)     /* 221184 B */

#define MMA_BF16(c, a0,a1,a2,a3, b0,b1)                                      \
    asm volatile("mma.sync.aligned.m16n8k16.row.col.f32.bf16.bf16.f32 "      \
        "{%0,%1,%2,%3}, {%4,%5,%6,%7}, {%8,%9}, {%0,%1,%2,%3};"              \
        : "+f"(c[0]), "+f"(c[1]), "+f"(c[2]), "+f"(c[3])                     \
        : "r"(a0), "r"(a1), "r"(a2), "r"(a3), "r"(b0), "r"(b1))

__device__ __forceinline__ void cp_async16(uint32_t* smem_ptr, const void* gptr) {
    uint32_t s = (uint32_t)__cvta_generic_to_shared(smem_ptr);
    asm volatile("cp.async.cg.shared.global [%0], [%1], 16;" :: "r"(s), "l"(gptr));
}

__device__ __forceinline__ void gemm_bf3(
    const __nv_bfloat16* __restrict__ Ah, const __nv_bfloat16* __restrict__ Al,
    const __nv_bfloat16* __restrict__ Bh, const __nv_bfloat16* __restrict__ Bl,
    float* __restrict__ C, int K, int ldc, int bm0, int bn0, uint32_t* sm)
{
    /* stage layout (words): Ah[0,A_ST) Al[A_ST,2A_ST) Bh[2A_ST,+B_ST) Bl[...] */
    const int tid  = threadIdx.x;
    const int lane = tid & 31;
    const int wid  = tid >> 5;
    const int wm   = (wid & 1) * 64;
    const int wn   = (wid >> 1) * 64;
    const int t4   = lane & 3;
    const int g    = lane >> 2;

    float acc[4][8][4];
    #pragma unroll
    for (int i = 0; i < 4; i++)
        #pragma unroll
        for (int j = 0; j < 8; j++)
            #pragma unroll
            for (int r = 0; r < 4; r++) acc[i][j][r] = 0.f;

    const int T = K / GBK;

    /* staging: A 1024 chunks/array (4/thread), B 2048 chunks/array (8/thread = row tid) */
    #define STAGE_TILE(ti, buf) do {                                                     \
        const int _k0 = (ti) * GBK;                                                      \
        uint32_t* _sb = sm + (buf) * STAGE_W;                                            \
        _Pragma("unroll")                                                                \
        for (int s = 0; s < 4; s++) {                                                    \
            int _c = tid * 4 + s;                                                        \
            int _r = _c >> 3, _ch = _c & 7;                                              \
            cp_async16(_sb + _r * STRW + _ch * 4,                                        \
                       (const char*)(Ah + (size_t)(bm0 + _r) * K + _k0) + _ch * 16);     \
            cp_async16(_sb + A_ST + _r * STRW + _ch * 4,                                 \
                       (const char*)(Al + (size_t)(bm0 + _r) * K + _k0) + _ch * 16);     \
        }                                                                                \
        _Pragma("unroll")                                                                \
        for (int s = 0; s < 8; s++) {                                                    \
            cp_async16(_sb + 2 * A_ST + tid * STRW + s * 4,                              \
                       (const char*)(Bh + (size_t)(bn0 + tid) * K + _k0) + s * 16);      \
            cp_async16(_sb + 2 * A_ST + B_ST + tid * STRW + s * 4,                       \
                       (const char*)(Bl + (size_t)(bn0 + tid) * K + _k0) + s * 16);      \
        }                                                                                \
    } while (0)

    STAGE_TILE(0, 0);
    asm volatile("cp.async.commit_group;");

    for (int t = 0; t < T; t++) {
        const int buf = t & 1;
        if (t + 1 < T) {
            STAGE_TILE(t + 1, (t + 1) & 1);
            asm volatile("cp.async.commit_group;");
            asm volatile("cp.async.wait_group 1;");
        } else {
            asm volatile("cp.async.wait_group 0;");
        }
        __syncthreads();

        const uint32_t* AhS = sm + buf * STAGE_W;
        const uint32_t* AlS = AhS + A_ST;
        const uint32_t* BhS = AhS + 2 * A_ST;
        const uint32_t* BlS = BhS + B_ST;

        #pragma unroll
        for (int ks = 0; ks < 4; ks++) {
            const int kw = ks * 8;
            uint32_t ah[4][4], al[4][4], bh[8][2], bl[8][2];
            #pragma unroll
            for (int i = 0; i < 4; i++) {
                const int mr = wm + i * 16 + g;
                ah[i][0] = AhS[mr * STRW + kw + t4];
                ah[i][1] = AhS[(mr + 8) * STRW + kw + t4];
                ah[i][2] = AhS[mr * STRW + kw + t4 + 4];
                ah[i][3] = AhS[(mr + 8) * STRW + kw + t4 + 4];
                al[i][0] = AlS[mr * STRW + kw + t4];
                al[i][1] = AlS[(mr + 8) * STRW + kw + t4];
                al[i][2] = AlS[mr * STRW + kw + t4 + 4];
                al[i][3] = AlS[(mr + 8) * STRW + kw + t4 + 4];
            }
            #pragma unroll
            for (int j = 0; j < 8; j++) {
                const int nc = wn + j * 8 + g;
                bh[j][0] = BhS[nc * STRW + kw + t4];
                bh[j][1] = BhS[nc * STRW + kw + t4 + 4];
                bl[j][0] = BlS[nc * STRW + kw + t4];
                bl[j][1] = BlS[nc * STRW + kw + t4 + 4];
            }
            #pragma unroll
            for (int i = 0; i < 4; i++)
                #pragma unroll
                for (int j = 0; j < 8; j++) {
                    MMA_BF16(acc[i][j], ah[i][0], ah[i][1], ah[i][2], ah[i][3], bh[j][0], bh[j][1]);
                    MMA_BF16(acc[i][j], ah[i][0], ah[i][1], ah[i][2], ah[i][3], bl[j][0], bl[j][1]);
                    MMA_BF16(acc[i][j], al[i][0], al[i][1], al[i][2], al[i][3], bh[j][0], bh[j][1]);
                }
        }
        __syncthreads();
    }
    #undef STAGE_TILE

    #pragma unroll
    for (int i = 0; i < 4; i++) {
        int row0 = bm0 + wm + i * 16 + g;
        #pragma unroll
        for (int j = 0; j < 8; j++) {
            int col = bn0 + wn + j * 8 + 2 * t4;
            *(float2*)(C + (size_t)row0 * ldc + col)       = make_float2(acc[i][j][0], acc[i][j][1]);
            *(float2*)(C + (size_t)(row0 + 8) * ldc + col) = make_float2(acc[i][j][2], acc[i][j][3]);
        }
    }
}

/* fused QKV: grid.x = 24 (16 Q + 4 K + 4 V n-strips of 256), grid.y = 16 */
__global__ __launch_bounds__(256, 1) void qkv_gemm_kernel()
{
    extern __shared__ uint32_t sm[];
    const int bx = blockIdx.x;
    const int bm0 = blockIdx.y * GBM;
    if (bx < 16)
        gemm_bf3(g_hsh, g_hsl, g_wqh, g_wql, g_q, HIDDEN, QDIM, bm0, bx * GBN, sm);
    else if (bx < 20)
        gemm_bf3(g_hsh, g_hsl, g_wkh, g_wkl, g_k, HIDDEN, KVDIM, bm0, (bx - 16) * GBN, sm);
    else
        gemm_bf3(g_hsh, g_hsl, g_wvh, g_wvl, g_v, HIDDEN, KVDIM, bm0, (bx - 20) * GBN, sm);
}

__global__ __launch_bounds__(256, 1) void o_gemm_kernel(float* __restrict__ out)
{
    extern __shared__ uint32_t sm[];
    gemm_bf3(g_ath, g_atl, g_woh, g_wol, out, QDIM, HIDDEN, blockIdx.y * GBM, blockIdx.x * GBN, sm);
}

/* ------------------------- RoPE (NeoX) ------------------------- */
__global__ void rope_kernel(float* x, const int* __restrict__ positions, int nheads)
{
    int idx = blockIdx.x * blockDim.x + threadIdx.x;
    int total = SEQ * nheads * (HD / 2);
    if (idx >= total) return;
    int i = idx & 63;
    int h = (idx >> 6) % nheads;
    int s = idx / (64 * nheads);
    float inv = powf(1000000.0f, -(float)i * (1.0f / 64.0f));
    float f = (float)positions[s] * inv;
    float c = cosf(f), sn = sinf(f);
    float* base = x + ((size_t)s * nheads + h) * HD;
    float x1 = base[i], x2 = base[i + 64];
    base[i]      = x1 * c - x2 * sn;
    base[i + 64] = x2 * c + x1 * sn;
}

/* ------------------------- Attention: bf16x3 mma flash (passing since R3) -------------- */
#define AQT 128
#define AKT 64
#define KPAD 68
#define VPAD 136

__global__ __launch_bounds__(256, 1) void attn_mma_kernel(const float* __restrict__ sink)
{
    extern __shared__ uint32_t smw[];
    uint32_t* Qh = smw;
    uint32_t* Ql = Qh + AQT * KPAD;
    uint32_t* Kh = Ql + AQT * KPAD;
    uint32_t* Kl = Kh + AKT * KPAD;
    uint32_t* Vh = Kl + AKT * KPAD;
    uint32_t* Vl = Vh + (AKT/2) * VPAD;

    const int h   = blockIdx.y;
    const int q0  = blockIdx.x * AQT;
    const int kvh = h >> 2;
    const int tid = threadIdx.x;
    const int lane = tid & 31;
    const int wid  = tid >> 5;
    const int wrow = wid * 16;
    const int t4   = lane & 3;
    const int g    = lane >> 2;

    {
        const float* Qg = g_q + (size_t)q0 * QDIM + h * HD;
        #pragma unroll
        for (int it = 0; it < 16; it++) {
            int slot = tid + it * 256;
            int r = slot >> 5, d4 = slot & 31;
            float4 v = *(const float4*)(Qg + (size_t)r * QDIM + d4 * 4);
            uint32_t h01, l01, h23, l23;
            split2(v.x, v.y, h01, l01);
            split2(v.z, v.w, h23, l23);
            Qh[r * KPAD + d4 * 2]     = h01;
            Qh[r * KPAD + d4 * 2 + 1] = h23;
            Ql[r * KPAD + d4 * 2]     = l01;
            Ql[r * KPAD + d4 * 2 + 1] = l23;
        }
    }

    float o[16][4];
    #pragma unroll
    for (int i = 0; i < 16; i++)
        #pragma unroll
        for (int r = 0; r < 4; r++) o[i][r] = 0.f;
    float l0 = 0.f, l1 = 0.f;

    int jlo = q0 - (WINDOW - 1);
    if (jlo < 0) jlo = 0;
    int kt0 = (jlo / AKT) * AKT;

    const int qi0 = q0 + wrow + g;
    const int qi1 = qi0 + 8;

    for (int kt = kt0; kt < q0 + AQT; kt += AKT) {
        __syncthreads();
        {
            const float* Kg = g_k + (size_t)kt * KVDIM + kvh * HD;
            #pragma unroll
            for (int it = 0; it < 8; it++) {
                int slot = tid + it * 256;
                int r = slot >> 5, d4 = slot & 31;
                float4 v = *(const float4*)(Kg + (size_t)r * KVDIM + d4 * 4);
                uint32_t h01, l01, h23, l23;
                split2(v.x, v.y, h01, l01);
                split2(v.z, v.w, h23, l23);
                Kh[r * KPAD + d4 * 2]     = h01;
                Kh[r * KPAD + d4 * 2 + 1] = h23;
                Kl[r * KPAD + d4 * 2]     = l01;
                Kl[r * KPAD + d4 * 2 + 1] = l23;
            }
        }
        {
            const float* Vg = g_v + (size_t)kt * KVDIM + kvh * HD;
            #pragma unroll
            for (int it = 0; it < 4; it++) {
                int slot = tid + it * 256;
                int rp = slot >> 5, d4 = slot & 31;
                float4 v0 = *(const float4*)(Vg + (size_t)(2 * rp) * KVDIM + d4 * 4);
                float4 v1 = *(const float4*)(Vg + (size_t)(2 * rp + 1) * KVDIM + d4 * 4);
                const float* a = &v0.x;
                const float* b = &v1.x;
                #pragma unroll
                for (int jj = 0; jj < 4; jj++) {
                    uint32_t hi, lo;
                    split2(a[jj], b[jj], hi, lo);
                    Vh[rp * VPAD + d4 * 4 + jj] = hi;
                    Vl[rp * VPAD + d4 * 4 + jj] = lo;
                }
            }
        }
        __syncthreads();

        float s[8][4];
        #pragma unroll
        for (int nt = 0; nt < 8; nt++)
            #pragma unroll
            for (int r = 0; r < 4; r++) s[nt][r] = 0.f;

        #pragma unroll
        for (int kk = 0; kk < 8; kk++) {
            const int kw = kk * 8;
            uint32_t ah0 = Qh[(wrow + g)     * KPAD + kw + t4];
            uint32_t ah1 = Qh[(wrow + g + 8) * KPAD + kw + t4];
            uint32_t ah2 = Qh[(wrow + g)     * KPAD + kw + t4 + 4];
            uint32_t ah3 = Qh[(wrow + g + 8) * KPAD + kw + t4 + 4];
            uint32_t al0 = Ql[(wrow + g)     * KPAD + kw + t4];
            uint32_t al1 = Ql[(wrow + g + 8) * KPAD + kw + t4];
            uint32_t al2 = Ql[(wrow + g)     * KPAD + kw + t4 + 4];
            uint32_t al3 = Ql[(wrow + g + 8) * KPAD + kw + t4 + 4];
            #pragma unroll
            for (int nt = 0; nt < 8; nt++) {
                const int krow = nt * 8 + g;
                uint32_t bh0 = Kh[krow * KPAD + kw + t4];
                uint32_t bh1 = Kh[krow * KPAD + kw + t4 + 4];
                uint32_t bl0 = Kl[krow * KPAD + kw + t4];
                uint32_t bl1 = Kl[krow * KPAD + kw + t4 + 4];
                MMA_BF16(s[nt], ah0, ah1, ah2, ah3, bh0, bh1);
                MMA_BF16(s[nt], ah0, ah1, ah2, ah3, bl0, bl1);
                MMA_BF16(s[nt], al0, al1, al2, al3, bh0, bh1);
            }
        }

        #pragma unroll
        for (int nt = 0; nt < 8; nt++) {
            int c0 = kt + nt * 8 + 2 * t4;
            int c1 = c0 + 1;
            float p0 = (c0 <= qi0 && qi0 - c0 < WINDOW) ? __expf(s[nt][0] * SCALING) : 0.f;
            float p1 = (c1 <= qi0 && qi0 - c1 < WINDOW) ? __expf(s[nt][1] * SCALING) : 0.f;
            float p2 = (c0 <= qi1 && qi1 - c0 < WINDOW) ? __expf(s[nt][2] * SCALING) : 0.f;
            float p3 = (c1 <= qi1 && qi1 - c1 < WINDOW) ? __expf(s[nt][3] * SCALING) : 0.f;
            l0 += p0 + p1;
            l1 += p2 + p3;
            s[nt][0] = p0; s[nt][1] = p1; s[nt][2] = p2; s[nt][3] = p3;
        }

        #pragma unroll
        for (int ks = 0; ks < 4; ks++) {
            uint32_t ah0, al0, ah1, al1, ah2, al2, ah3, al3;
            split2(s[2*ks][0],   s[2*ks][1],   ah0, al0);
            split2(s[2*ks][2],   s[2*ks][3],   ah1, al1);
            split2(s[2*ks+1][0], s[2*ks+1][1], ah2, al2);
            split2(s[2*ks+1][2], s[2*ks+1][3], ah3, al3);
            #pragma unroll
            for (int nt = 0; nt < 16; nt++) {
                uint32_t bh0 = Vh[(ks * 8 + t4)     * VPAD + nt * 8 + g];
                uint32_t bh1 = Vh[(ks * 8 + t4 + 4) * VPAD + nt * 8 + g];
                uint32_t bl0 = Vl[(ks * 8 + t4)     * VPAD + nt * 8 + g];
                uint32_t bl1 = Vl[(ks * 8 + t4 + 4) * VPAD + nt * 8 + g];
                MMA_BF16(o[nt], ah0, ah1, ah2, ah3, bh0, bh1);
                MMA_BF16(o[nt], ah0, ah1, ah2, ah3, bl0, bl1);
                MMA_BF16(o[nt], al0, al1, al2, al3, bh0, bh1);
            }
        }
    }

    l0 += __shfl_xor_sync(0xffffffffu, l0, 1);
    l0 += __shfl_xor_sync(0xffffffffu, l0, 2);
    l1 += __shfl_xor_sync(0xffffffffu, l1, 1);
    l1 += __shfl_xor_sync(0xffffffffu, l1, 2);
    float sk = __expf(sink[h]);
    float inv0 = 1.0f / (l0 + sk);
    float inv1 = 1.0f / (l1 + sk);

    /* write hi/lo bf16 directly for the bf16x3 O-projection */
    __nv_bfloat16* oh0 = g_ath + (size_t)qi0 * QDIM + h * HD;
    __nv_bfloat16* ol0 = g_atl + (size_t)qi0 * QDIM + h * HD;
    __nv_bfloat16* oh1 = g_ath + (size_t)qi1 * QDIM + h * HD;
    __nv_bfloat16* ol1 = g_atl + (size_t)qi1 * QDIM + h * HD;
    #pragma unroll
    for (int nt = 0; nt < 16; nt++) {
        int d = nt * 8 + 2 * t4;
        uint32_t hi, lo;
        split2(o[nt][0] * inv0, o[nt][1] * inv0, hi, lo);
        *(uint32_t*)(oh0 + d) = hi;
        *(uint32_t*)(ol0 + d) = lo;
        split2(o[nt][2] * inv1, o[nt][3] * inv1, hi, lo);
        *(uint32_t*)(oh1 + d) = hi;
        *(uint32_t*)(ol1 + d) = lo;
    }
}

/* ------------------------- launch ------------------------- */
extern "C" void kernel_launch(void* const* d_in, const int* in_sizes, int n_in,
                              void* d_out, int out_size)
{
    const float* hs   = (const float*)d_in[0];
    const int*   pos  = (const int*)d_in[1];
    const float* wq   = (const float*)d_in[2];
    const float* wk   = (const float*)d_in[3];
    const float* wv   = (const float*)d_in[4];
    const float* wo   = (const float*)d_in[5];
    const float* sink = (const float*)d_in[6];
    float* out = (float*)d_out;

    float *q_ptr, *k_ptr;
    __nv_bfloat16 *hsh_p, *hsl_p, *wqh_p, *wql_p, *wkh_p, *wkl_p, *wvh_p, *wvl_p, *woh_p, *wol_p;
    cudaGetSymbolAddress((void**)&q_ptr, g_q);
    cudaGetSymbolAddress((void**)&k_ptr, g_k);
    cudaGetSymbolAddress((void**)&hsh_p, g_hsh);
    cudaGetSymbolAddress((void**)&hsl_p, g_hsl);
    cudaGetSymbolAddress((void**)&wqh_p, g_wqh);
    cudaGetSymbolAddress((void**)&wql_p, g_wql);
    cudaGetSymbolAddress((void**)&wkh_p, g_wkh);
    cudaGetSymbolAddress((void**)&wkl_p, g_wkl);
    cudaGetSymbolAddress((void**)&wvh_p, g_wvh);
    cudaGetSymbolAddress((void**)&wvl_p, g_wvl);
    cudaGetSymbolAddress((void**)&woh_p, g_woh);
    cudaGetSymbolAddress((void**)&wol_p, g_wol);

    cudaFuncSetAttribute(qkv_gemm_kernel, cudaFuncAttributeMaxDynamicSharedMemorySize, GEMM_SMEM);
    cudaFuncSetAttribute(o_gemm_kernel,   cudaFuncAttributeMaxDynamicSharedMemorySize, GEMM_SMEM);

    /* operand splits */
    split_a_kernel<<<(SEQ*HIDDEN/4 + 255)/256, 256>>>(hs, hsh_p, hsl_p, SEQ*HIDDEN/4);
    {
        dim3 blk(32, 8);
        split_bt_kernel<<<dim3(QDIM/32,  HIDDEN/32), blk>>>(wq, wqh_p, wql_p, HIDDEN, QDIM);
        split_bt_kernel<<<dim3(KVDIM/32, HIDDEN/32), blk>>>(wk, wkh_p, wkl_p, HIDDEN, KVDIM);
        split_bt_kernel<<<dim3(KVDIM/32, HIDDEN/32), blk>>>(wv, wvh_p, wvl_p, HIDDEN, KVDIM);
        split_bt_kernel<<<dim3(HIDDEN/32, QDIM/32),  blk>>>(wo, woh_p, wol_p, QDIM, HIDDEN);
    }

    /* fused QKV projection (bf16x3 tensor cores) */
    qkv_gemm_kernel<<<dim3(24, SEQ / GBM), 256, GEMM_SMEM>>>();

    /* RoPE */
    {
        int tq = SEQ * NQH * (HD / 2);
        rope_kernel<<<(tq + 255) / 256, 256>>>(q_ptr, pos, NQH);
        int tk = SEQ * NKVH * (HD / 2);
        rope_kernel<<<(tk + 255) / 256, 256>>>(k_ptr, pos, NKVH);
    }

    /* attention (bf16x3 tensor cores) */
    {
        int smem_words = 2 * AQT * KPAD + 2 * AKT * KPAD + 2 * (AKT/2) * VPAD;
        int smem = smem_words * 4;
        cudaFuncSetAttribute(attn_mma_kernel, cudaFuncAttributeMaxDynamicSharedMemorySize, smem);
        attn_mma_kernel<<<dim3(SEQ / AQT, NQH), 256, smem>>>(sink);
    }

    /* output projection (bf16x3 tensor cores) */
    o_gemm_kernel<<<dim3(HIDDEN / GBN, SEQ / GBM), 256, GEMM_SMEM>>>(out);
}

// round 10
// speedup vs baseline: 1.6898x; 1.6898x over previous
#include <cuda_runtime.h>
#include <cuda_bf16.h>
#include <math.h>
#include <stdint.h>

#define SEQ 2048
#define HIDDEN 4096
#define NQH 32
#define NKVH 8
#define HD 128
#define QDIM (NQH*HD)      /* 4096 */
#define KVDIM (NKVH*HD)    /* 1024 */
#define WINDOW 1024
#define SCALING 0.08838834764831845f

/* scratch (allocation-free rule: __device__ globals) */
__device__ float g_q[SEQ*QDIM];
__device__ float g_k[SEQ*KVDIM];
__device__ float g_v[SEQ*KVDIM];
__device__ float g_attn[SEQ*QDIM];
/* tf32-pre-rounded GEMM operands */
__device__ float g_hs[SEQ*HIDDEN];
__device__ float g_wq[HIDDEN*QDIM];
__device__ float g_wk[HIDDEN*KVDIM];
__device__ float g_wv[HIDDEN*KVDIM];
__device__ float g_wo[QDIM*HIDDEN];

__device__ __forceinline__ float roundtf(float x) {
    float r;
    asm("cvt.rna.tf32.f32 %0, %1;" : "=f"(r) : "f"(x));
    return r;
}

/* elementwise tf32 rounding pass */
__global__ void round_tf32_kernel(const float* __restrict__ in, float* __restrict__ out, int n4)
{
    int i = blockIdx.x * blockDim.x + threadIdx.x;
    if (i >= n4) return;
    float4 v = ((const float4*)in)[i];
    v.x = roundtf(v.x); v.y = roundtf(v.y);
    v.z = roundtf(v.z); v.w = roundtf(v.w);
    ((float4*)out)[i] = v;
}

/* ---------------- TF32 GEMM: 128x256 CTA, 8 warps 64x64, 4-stage cp.async ---------------- */
/* Inputs MUST be tf32-pre-rounded fp32 (mma reads raw bits; truncation == identity).
   Single __syncthreads per k-iteration: 4 buffers, staging distance 2.                     */

#define GBM 128
#define GBN 256
#define GBK 32
#define ASTR 36                    /* floats */
#define BSTR 264                   /* floats; 264 mod 32 = 8 */
#define A_STAGE (GBM*ASTR)         /* 4608  */
#define B_STAGE (GBK*BSTR)         /* 8448  */
#define STG 4
#define GEMM_SMEM (STG*(A_STAGE+B_STAGE)*4)   /* 208896 B */

__device__ __forceinline__ void cp_async16(float* smem_ptr, const float* gptr) {
    uint32_t s = (uint32_t)__cvta_generic_to_shared(smem_ptr);
    asm volatile("cp.async.cg.shared.global [%0], [%1], 16;" :: "r"(s), "l"(gptr));
}

__device__ __forceinline__ void gemm_body(
    const float* __restrict__ A, const float* __restrict__ B, float* __restrict__ C,
    int ldb, int ldc, int K, int bm0, int bn0, float* sm)
{
    float* As = sm;                    /* [STG][128][ASTR] */
    float* Bs = sm + STG * A_STAGE;    /* [STG][32][BSTR]  */

    const int tid  = threadIdx.x;
    const int lane = tid & 31;
    const int wid  = tid >> 5;
    const int wm   = (wid & 1) * 64;
    const int wn   = (wid >> 1) * 64;
    const int t4   = lane & 3;
    const int g    = lane >> 2;

    float acc[4][8][4];
    #pragma unroll
    for (int i = 0; i < 4; i++)
        #pragma unroll
        for (int j = 0; j < 8; j++)
            #pragma unroll
            for (int r = 0; r < 4; r++) acc[i][j][r] = 0.f;

    /* staging maps: A 1024 chunks (4/thread), B 2048 chunks (8/thread) */
    const int ar = tid >> 1;         /* 0..127 */
    const int ac = (tid & 1) * 4;    /* chunk base 0 or 4 */
    const int br = tid >> 3;         /* 0..31  */
    const int bc = tid & 7;          /* 0..7   */

    const int T = K / GBK;

    #define STAGE_TILE(ti, buf) do {                                              \
        const int _k0 = (ti) * GBK;                                               \
        const float* _Ag = A + (size_t)(bm0 + ar) * K + _k0;                      \
        _Pragma("unroll")                                                         \
        for (int s = 0; s < 4; s++)                                               \
            cp_async16(&As[(buf)*A_STAGE + ar*ASTR + (ac + s)*4], _Ag + (ac + s)*4);\
        const float* _Bg = B + (size_t)(_k0 + br) * ldb + bn0;                    \
        _Pragma("unroll")                                                         \
        for (int s = 0; s < 8; s++)                                               \
            cp_async16(&Bs[(buf)*B_STAGE + br*BSTR + (bc + s*8)*4], _Bg + (bc + s*8)*4);\
    } while (0)

    STAGE_TILE(0, 0);
    asm volatile("cp.async.commit_group;");
    STAGE_TILE(1, 1);
    asm volatile("cp.async.commit_group;");

    for (int t = 0; t < T; t++) {
        const int buf = t & 3;
        if (t + 2 < T)
            STAGE_TILE(t + 2, (t + 2) & 3);
        asm volatile("cp.async.commit_group;");   /* uniform group count (may be empty) */
        asm volatile("cp.async.wait_group 2;");   /* group t complete */
        __syncthreads();                          /* single barrier per iteration */

        const uint32_t* Ab = (const uint32_t*)(As + buf * A_STAGE);
        const uint32_t* Bb = (const uint32_t*)(Bs + buf * B_STAGE);

        #pragma unroll
        for (int ks = 0; ks < 4; ks++) {
            const int kk = ks * 8;
            uint32_t a[4][4], b[8][2];
            #pragma unroll
            for (int i = 0; i < 4; i++) {
                const int mr = wm + i * 16 + g;
                a[i][0] = Ab[mr * ASTR + kk + t4];
                a[i][1] = Ab[(mr + 8) * ASTR + kk + t4];
                a[i][2] = Ab[mr * ASTR + kk + t4 + 4];
                a[i][3] = Ab[(mr + 8) * ASTR + kk + t4 + 4];
            }
            #pragma unroll
            for (int j = 0; j < 8; j++) {
                const int nc = wn + j * 8 + g;
                b[j][0] = Bb[(kk + t4) * BSTR + nc];
                b[j][1] = Bb[(kk + t4 + 4) * BSTR + nc];
            }
            #pragma unroll
            for (int i = 0; i < 4; i++)
                #pragma unroll
                for (int j = 0; j < 8; j++) {
                    asm volatile(
                        "mma.sync.aligned.m16n8k8.row.col.f32.tf32.tf32.f32 "
                        "{%0,%1,%2,%3}, {%4,%5,%6,%7}, {%8,%9}, {%0,%1,%2,%3};"
                        : "+f"(acc[i][j][0]), "+f"(acc[i][j][1]),
                          "+f"(acc[i][j][2]), "+f"(acc[i][j][3])
                        : "r"(a[i][0]), "r"(a[i][1]), "r"(a[i][2]), "r"(a[i][3]),
                          "r"(b[j][0]), "r"(b[j][1]));
                }
        }
    }
    #undef STAGE_TILE

    #pragma unroll
    for (int i = 0; i < 4; i++) {
        int row0 = bm0 + wm + i * 16 + g;
        #pragma unroll
        for (int j = 0; j < 8; j++) {
            int col = bn0 + wn + j * 8 + 2 * t4;
            *(float2*)(C + (size_t)row0 * ldc + col)       = make_float2(acc[i][j][0], acc[i][j][1]);
            *(float2*)(C + (size_t)(row0 + 8) * ldc + col) = make_float2(acc[i][j][2], acc[i][j][3]);
        }
    }
}

/* fused QKV: grid.x = 24 (16 Q cols + 4 K + 4 V), grid.y = 16 */
__global__ __launch_bounds__(256, 1) void qkv_gemm_kernel()
{
    extern __shared__ float sm[];
    const int bx = blockIdx.x;
    const int bm0 = blockIdx.y * GBM;
    if (bx < 16)
        gemm_body(g_hs, g_wq, g_q, QDIM, QDIM, HIDDEN, bm0, bx * GBN, sm);
    else if (bx < 20)
        gemm_body(g_hs, g_wk, g_k, KVDIM, KVDIM, HIDDEN, bm0, (bx - 16) * GBN, sm);
    else
        gemm_body(g_hs, g_wv, g_v, KVDIM, KVDIM, HIDDEN, bm0, (bx - 20) * GBN, sm);
}

__global__ __launch_bounds__(256, 1) void o_gemm_kernel(float* __restrict__ out)
{
    extern __shared__ float sm[];
    gemm_body(g_attn, g_wo, out, HIDDEN, HIDDEN, QDIM, blockIdx.y * GBM, blockIdx.x * GBN, sm);
}

/* ------------------------- RoPE (NeoX) ------------------------- */
__global__ void rope_kernel(float* x, const int* __restrict__ positions, int nheads)
{
    int idx = blockIdx.x * blockDim.x + threadIdx.x;
    int total = SEQ * nheads * (HD / 2);
    if (idx >= total) return;
    int i = idx & 63;
    int h = (idx >> 6) % nheads;
    int s = idx / (64 * nheads);
    float inv = powf(1000000.0f, -(float)i * (1.0f / 64.0f));
    float f = (float)positions[s] * inv;
    float c = cosf(f), sn = sinf(f);
    float* base = x + ((size_t)s * nheads + h) * HD;
    float x1 = base[i], x2 = base[i + 64];
    base[i]      = x1 * c - x2 * sn;
    base[i + 64] = x2 * c + x1 * sn;
}

/* ------------------------- Attention: bf16x3 tensor-core flash ------------------------- */
#define AQT 128
#define AKT 64
#define KPAD 68
#define VPAD 136

#define MMA_BF16(c, a0,a1,a2,a3, b0,b1)                                      \
    asm volatile("mma.sync.aligned.m16n8k16.row.col.f32.bf16.bf16.f32 "      \
        "{%0,%1,%2,%3}, {%4,%5,%6,%7}, {%8,%9}, {%0,%1,%2,%3};"              \
        : "+f"(c[0]), "+f"(c[1]), "+f"(c[2]), "+f"(c[3])                     \
        : "r"(a0), "r"(a1), "r"(a2), "r"(a3), "r"(b0), "r"(b1))

__device__ __forceinline__ void split2(float x, float y, uint32_t& hi, uint32_t& lo) {
    __nv_bfloat162 h = __float22bfloat162_rn(make_float2(x, y));
    float rx = x - __bfloat162float(h.x);
    float ry = y - __bfloat162float(h.y);
    __nv_bfloat162 l = __float22bfloat162_rn(make_float2(rx, ry));
    hi = *(uint32_t*)&h;
    lo = *(uint32_t*)&l;
}

__global__ __launch_bounds__(256, 1) void attn_mma_kernel(const float* __restrict__ sink)
{
    extern __shared__ uint32_t smw[];
    uint32_t* Qh = smw;
    uint32_t* Ql = Qh + AQT * KPAD;
    uint32_t* Kh = Ql + AQT * KPAD;
    uint32_t* Kl = Kh + AKT * KPAD;
    uint32_t* Vh = Kl + AKT * KPAD;
    uint32_t* Vl = Vh + (AKT/2) * VPAD;

    const int h   = blockIdx.y;
    const int q0  = blockIdx.x * AQT;
    const int kvh = h >> 2;
    const int tid = threadIdx.x;
    const int lane = tid & 31;
    const int wid  = tid >> 5;
    const int wrow = wid * 16;
    const int t4   = lane & 3;
    const int g    = lane >> 2;

    {
        const float* Qg = g_q + (size_t)q0 * QDIM + h * HD;
        #pragma unroll
        for (int it = 0; it < 16; it++) {
            int slot = tid + it * 256;
            int r = slot >> 5, d4 = slot & 31;
            float4 v = *(const float4*)(Qg + (size_t)r * QDIM + d4 * 4);
            uint32_t h01, l01, h23, l23;
            split2(v.x, v.y, h01, l01);
            split2(v.z, v.w, h23, l23);
            Qh[r * KPAD + d4 * 2]     = h01;
            Qh[r * KPAD + d4 * 2 + 1] = h23;
            Ql[r * KPAD + d4 * 2]     = l01;
            Ql[r * KPAD + d4 * 2 + 1] = l23;
        }
    }

    float o[16][4];
    #pragma unroll
    for (int i = 0; i < 16; i++)
        #pragma unroll
        for (int r = 0; r < 4; r++) o[i][r] = 0.f;
    float l0 = 0.f, l1 = 0.f;

    int jlo = q0 - (WINDOW - 1);
    if (jlo < 0) jlo = 0;
    int kt0 = (jlo / AKT) * AKT;

    const int qi0 = q0 + wrow + g;
    const int qi1 = qi0 + 8;

    for (int kt = kt0; kt < q0 + AQT; kt += AKT) {
        __syncthreads();
        {
            const float* Kg = g_k + (size_t)kt * KVDIM + kvh * HD;
            #pragma unroll
            for (int it = 0; it < 8; it++) {
                int slot = tid + it * 256;
                int r = slot >> 5, d4 = slot & 31;
                float4 v = *(const float4*)(Kg + (size_t)r * KVDIM + d4 * 4);
                uint32_t h01, l01, h23, l23;
                split2(v.x, v.y, h01, l01);
                split2(v.z, v.w, h23, l23);
                Kh[r * KPAD + d4 * 2]     = h01;
                Kh[r * KPAD + d4 * 2 + 1] = h23;
                Kl[r * KPAD + d4 * 2]     = l01;
                Kl[r * KPAD + d4 * 2 + 1] = l23;
            }
        }
        {
            const float* Vg = g_v + (size_t)kt * KVDIM + kvh * HD;
            #pragma unroll
            for (int it = 0; it < 4; it++) {
                int slot = tid + it * 256;
                int rp = slot >> 5, d4 = slot & 31;
                float4 v0 = *(const float4*)(Vg + (size_t)(2 * rp) * KVDIM + d4 * 4);
                float4 v1 = *(const float4*)(Vg + (size_t)(2 * rp + 1) * KVDIM + d4 * 4);
                const float* a = &v0.x;
                const float* b = &v1.x;
                #pragma unroll
                for (int jj = 0; jj < 4; jj++) {
                    uint32_t hi, lo;
                    split2(a[jj], b[jj], hi, lo);
                    Vh[rp * VPAD + d4 * 4 + jj] = hi;
                    Vl[rp * VPAD + d4 * 4 + jj] = lo;
                }
            }
        }
        __syncthreads();

        float s[8][4];
        #pragma unroll
        for (int nt = 0; nt < 8; nt++)
            #pragma unroll
            for (int r = 0; r < 4; r++) s[nt][r] = 0.f;

        #pragma unroll
        for (int kk = 0; kk < 8; kk++) {
            const int kw = kk * 8;
            uint32_t ah0 = Qh[(wrow + g)     * KPAD + kw + t4];
            uint32_t ah1 = Qh[(wrow + g + 8) * KPAD + kw + t4];
            uint32_t ah2 = Qh[(wrow + g)     * KPAD + kw + t4 + 4];
            uint32_t ah3 = Qh[(wrow + g + 8) * KPAD + kw + t4 + 4];
            uint32_t al0 = Ql[(wrow + g)     * KPAD + kw + t4];
            uint32_t al1 = Ql[(wrow + g + 8) * KPAD + kw + t4];
            uint32_t al2 = Ql[(wrow + g)     * KPAD + kw + t4 + 4];
            uint32_t al3 = Ql[(wrow + g + 8) * KPAD + kw + t4 + 4];
            #pragma unroll
            for (int nt = 0; nt < 8; nt++) {
                const int krow = nt * 8 + g;
                uint32_t bh0 = Kh[krow * KPAD + kw + t4];
                uint32_t bh1 = Kh[krow * KPAD + kw + t4 + 4];
                uint32_t bl0 = Kl[krow * KPAD + kw + t4];
                uint32_t bl1 = Kl[krow * KPAD + kw + t4 + 4];
                MMA_BF16(s[nt], ah0, ah1, ah2, ah3, bh0, bh1);
                MMA_BF16(s[nt], ah0, ah1, ah2, ah3, bl0, bl1);
                MMA_BF16(s[nt], al0, al1, al2, al3, bh0, bh1);
            }
        }

        #pragma unroll
        for (int nt = 0; nt < 8; nt++) {
            int c0 = kt + nt * 8 + 2 * t4;
            int c1 = c0 + 1;
            float p0 = (c0 <= qi0 && qi0 - c0 < WINDOW) ? __expf(s[nt][0] * SCALING) : 0.f;
            float p1 = (c1 <= qi0 && qi0 - c1 < WINDOW) ? __expf(s[nt][1] * SCALING) : 0.f;
            float p2 = (c0 <= qi1 && qi1 - c0 < WINDOW) ? __expf(s[nt][2] * SCALING) : 0.f;
            float p3 = (c1 <= qi1 && qi1 - c1 < WINDOW) ? __expf(s[nt][3] * SCALING) : 0.f;
            l0 += p0 + p1;
            l1 += p2 + p3;
            s[nt][0] = p0; s[nt][1] = p1; s[nt][2] = p2; s[nt][3] = p3;
        }

        #pragma unroll
        for (int ks = 0; ks < 4; ks++) {
            uint32_t ah0, al0, ah1, al1, ah2, al2, ah3, al3;
            split2(s[2*ks][0],   s[2*ks][1],   ah0, al0);
            split2(s[2*ks][2],   s[2*ks][3],   ah1, al1);
            split2(s[2*ks+1][0], s[2*ks+1][1], ah2, al2);
            split2(s[2*ks+1][2], s[2*ks+1][3], ah3, al3);
            #pragma unroll
            for (int nt = 0; nt < 16; nt++) {
                uint32_t bh0 = Vh[(ks * 8 + t4)     * VPAD + nt * 8 + g];
                uint32_t bh1 = Vh[(ks * 8 + t4 + 4) * VPAD + nt * 8 + g];
                uint32_t bl0 = Vl[(ks * 8 + t4)     * VPAD + nt * 8 + g];
                uint32_t bl1 = Vl[(ks * 8 + t4 + 4) * VPAD + nt * 8 + g];
                MMA_BF16(o[nt], ah0, ah1, ah2, ah3, bh0, bh1);
                MMA_BF16(o[nt], ah0, ah1, ah2, ah3, bl0, bl1);
                MMA_BF16(o[nt], al0, al1, al2, al3, bh0, bh1);
            }
        }
    }

    l0 += __shfl_xor_sync(0xffffffffu, l0, 1);
    l0 += __shfl_xor_sync(0xffffffffu, l0, 2);
    l1 += __shfl_xor_sync(0xffffffffu, l1, 1);
    l1 += __shfl_xor_sync(0xffffffffu, l1, 2);
    float sk = __expf(sink[h]);
    float inv0 = 1.0f / (l0 + sk);
    float inv1 = 1.0f / (l1 + sk);

    /* store tf32-rounded so the O-projection GEMM can consume raw bits */
    float* out0 = g_attn + (size_t)qi0 * QDIM + h * HD;
    float* out1 = g_attn + (size_t)qi1 * QDIM + h * HD;
    #pragma unroll
    for (int nt = 0; nt < 16; nt++) {
        int d = nt * 8 + 2 * t4;
        *(float2*)(out0 + d) = make_float2(roundtf(o[nt][0] * inv0), roundtf(o[nt][1] * inv0));
        *(float2*)(out1 + d) = make_float2(roundtf(o[nt][2] * inv1), roundtf(o[nt][3] * inv1));
    }
}

/* ------------------------- launch ------------------------- */
extern "C" void kernel_launch(void* const* d_in, const int* in_sizes, int n_in,
                              void* d_out, int out_size)
{
    const float* hs   = (const float*)d_in[0];
    const int*   pos  = (const int*)d_in[1];
    const float* wq   = (const float*)d_in[2];
    const float* wk   = (const float*)d_in[3];
    const float* wv   = (const float*)d_in[4];
    const float* wo   = (const float*)d_in[5];
    const float* sink = (const float*)d_in[6];
    float* out = (float*)d_out;

    float *q_ptr, *k_ptr, *hs_ptr, *wq_ptr, *wk_ptr, *wv_ptr, *wo_ptr;
    cudaGetSymbolAddress((void**)&q_ptr, g_q);
    cudaGetSymbolAddress((void**)&k_ptr, g_k);
    cudaGetSymbolAddress((void**)&hs_ptr, g_hs);
    cudaGetSymbolAddress((void**)&wq_ptr, g_wq);
    cudaGetSymbolAddress((void**)&wk_ptr, g_wk);
    cudaGetSymbolAddress((void**)&wv_ptr, g_wv);
    cudaGetSymbolAddress((void**)&wo_ptr, g_wo);

    cudaFuncSetAttribute(qkv_gemm_kernel, cudaFuncAttributeMaxDynamicSharedMemorySize, GEMM_SMEM);
    cudaFuncSetAttribute(o_gemm_kernel,  cudaFuncAttributeMaxDynamicSharedMemorySize, GEMM_SMEM);

    /* tf32 pre-rounding of GEMM inputs */
    round_tf32_kernel<<<(SEQ*HIDDEN/4 + 255)/256, 256>>>(hs, hs_ptr, SEQ*HIDDEN/4);
    round_tf32_kernel<<<(HIDDEN*QDIM/4 + 255)/256, 256>>>(wq, wq_ptr, HIDDEN*QDIM/4);
    round_tf32_kernel<<<(HIDDEN*KVDIM/4 + 255)/256, 256>>>(wk, wk_ptr, HIDDEN*KVDIM/4);
    round_tf32_kernel<<<(HIDDEN*KVDIM/4 + 255)/256, 256>>>(wv, wv_ptr, HIDDEN*KVDIM/4);
    round_tf32_kernel<<<(QDIM*HIDDEN/4 + 255)/256, 256>>>(wo, wo_ptr, QDIM*HIDDEN/4);

    /* fused QKV projection */
    qkv_gemm_kernel<<<dim3(24, SEQ / GBM), 256, GEMM_SMEM>>>();

    /* RoPE */
    {
        int tq = SEQ * NQH * (HD / 2);
        rope_kernel<<<(tq + 255) / 256, 256>>>(q_ptr, pos, NQH);
        int tk = SEQ * NKVH * (HD / 2);
        rope_kernel<<<(tk + 255) / 256, 256>>>(k_ptr, pos, NKVH);
    }

    /* attention (bf16x3 tensor cores) */
    {
        int smem_words = 2 * AQT * KPAD + 2 * AKT * KPAD + 2 * (AKT/2) * VPAD;
        int smem = smem_words * 4;
        cudaFuncSetAttribute(attn_mma_kernel, cudaFuncAttributeMaxDynamicSharedMemorySize, smem);
        attn_mma_kernel<<<dim3(SEQ / AQT, NQH), 256, smem>>>(sink);
    }

    /* output projection */
    o_gemm_kernel<<<dim3(HIDDEN / GBN, SEQ / GBM), 256, GEMM_SMEM>>>(out);
}